// round 16
// baseline (speedup 1.0000x reference)
#include <cuda_runtime.h>
#include <cuda_fp16.h>
#include <cstdint>
#include <cstddef>

// Problem constants
#define BB 256      // batch
#define SS 512      // encoder sequence length
#define FF 64       // feature dim
#define HH 1024     // hidden dim
#define GG 4096     // 4*H gate rows
#define KTOT 1088   // F + H
#define TT 64       // prediction length
#define NSTEP (SS + TT)

// Tiling: B (weights) smem-resident (17 x 8KB); A double-buffered; 4KB h-staging
#define BM 128
#define BN 64
#define BRES (17 * 8192)               // resident B: 139,264 B
#define ASTG 32768                     // one A stage: 2 x 16KB subs
#define HST_OFF (BRES + 2 * ASTG)      // h staging (4KB) / fc scratch
#define SMEM_BYTES (HST_OFF + 8192)

// ---------------- device globals ----------------
__device__ __align__(16) __half g_B_enc[GG * KTOT];   // enc weights fp16, rows j*4+g, K-major
__device__ __align__(16) __half g_B_dec[GG * KTOT];   // dec step-SS weights (has x part)
__device__ __align__(16) __half g_B_de[GG * HH];      // dec folded weights: Whh + Wih@Wfc
__device__ __align__(16) float g_br_enc[GG];          // combined bias, reordered
__device__ __align__(16) float g_br_dec[GG];
__device__ __align__(16) float g_br_de[GG];           // folded bias: b_dec + Wih@bfc
__device__ __align__(16) __half g_X[SS * BB * FF];    // encoder x, [t][b][f], fp16
__device__ __align__(16) __half g_H[3][BB * HH];      // hidden state fp16 (triple buffer)
__device__ __align__(16) unsigned g_done[2][64][8];   // per-CTA step-completion flags (padded)

// ---------------- helpers ----------------
__device__ __forceinline__ uint32_t smem_u32(const void* p) {
    return (uint32_t)__cvta_generic_to_shared(p);
}
// L2-only: activations change across steps (persistent kernel -> no L1 flush)
__device__ __forceinline__ void cp16cg(uint32_t dst, const void* src) {
    asm volatile("cp.async.cg.shared.global [%0], [%1], 16;\n" :: "r"(dst), "l"(src));
}
// L1-cached: immutable weights
__device__ __forceinline__ void cp16ca(uint32_t dst, const void* src) {
    asm volatile("cp.async.ca.shared.global [%0], [%1], 16;\n" :: "r"(dst), "l"(src));
}
__device__ __forceinline__ void cp_commit() { asm volatile("cp.async.commit_group;\n"); }
__device__ __forceinline__ void cp_wait0()  { asm volatile("cp.async.wait_group 0;\n" ::: "memory"); }

__device__ __forceinline__ float sigf(float x)   { return 1.f / (1.f + __expf(-x)); }
__device__ __forceinline__ float tanhf_(float x) { return 2.f / (1.f + __expf(-2.f * x)) - 1.f; }

__device__ __forceinline__ unsigned ld_acq(const unsigned* p) {
    unsigned v;
    asm volatile("ld.acquire.gpu.u32 %0, [%1];" : "=r"(v) : "l"(p) : "memory");
    return v;
}
__device__ __forceinline__ void st_rel(unsigned* p, unsigned v) {
    asm volatile("st.release.gpu.u32 [%0], %1;" :: "l"(p), "r"(v) : "memory");
}

__device__ __forceinline__ void ldsm4(uint32_t* r, uint32_t addr) {
    asm volatile("ldmatrix.sync.aligned.m8n8.x4.shared.b16 {%0,%1,%2,%3}, [%4];"
        : "=r"(r[0]), "=r"(r[1]), "=r"(r[2]), "=r"(r[3]) : "r"(addr));
}
__device__ __forceinline__ void mma16816(float* d, const uint32_t* a, uint32_t b0, uint32_t b1) {
    asm volatile(
        "mma.sync.aligned.m16n8k16.row.col.f32.f16.f16.f32 "
        "{%0,%1,%2,%3}, {%4,%5,%6,%7}, {%8,%9}, {%0,%1,%2,%3};"
        : "+f"(d[0]), "+f"(d[1]), "+f"(d[2]), "+f"(d[3])
        : "r"(a[0]), "r"(a[1]), "r"(a[2]), "r"(a[3]), "r"(b0), "r"(b1));
}

// pair barrier: the two warps sharing wm (64 threads), named barrier id wm+1
__device__ __forceinline__ void bar_pair(int wm) {
    asm volatile("bar.sync %0, %1;" :: "r"(wm + 1), "r"(64) : "memory");
}

// ---------------- prep kernels ----------------
__global__ void prep_w(const float* __restrict__ Wih, const float* __restrict__ Whh,
                       const float* __restrict__ bih, const float* __restrict__ bhh,
                       int dec)
{
    __half* B = dec ? g_B_dec : g_B_enc;
    float* br = dec ? g_br_dec : g_br_enc;
    const int total = GG * KTOT;
    for (int idx = blockIdx.x * blockDim.x + threadIdx.x; idx < total;
         idx += gridDim.x * blockDim.x) {
        int r = idx / KTOT, k = idx - r * KTOT;
        int j = r >> 2, gg = r & 3;
        int srow = gg * HH + j;
        float w = (k < FF) ? Wih[srow * FF + k] : Whh[(size_t)srow * HH + (k - FF)];
        B[idx] = __float2half_rn(w);
    }
    for (int r = blockIdx.x * blockDim.x + threadIdx.x; r < GG;
         r += gridDim.x * blockDim.x) {
        int j = r >> 2, gg = r & 3;
        br[r] = bih[gg * HH + j] + bhh[gg * HH + j];
    }
}

// folded decoder weights: W_eff = W_hh_dec + W_ih_dec @ Wfc ; b_eff = b_dec + W_ih_dec @ bfc
__global__ void prep_wcomb(const float* __restrict__ Wih_d, const float* __restrict__ Whh_d,
                           const float* __restrict__ bih_d, const float* __restrict__ bhh_d,
                           const float* __restrict__ Wfc, const float* __restrict__ bfc)
{
    __shared__ float wt[64][65];       // Wfc[f][k0+kk]
    const int k0 = blockIdx.x * 64;
    const int r0 = blockIdx.y * 256;
    const int tid = threadIdx.x;
    for (int i = tid; i < 64 * 64; i += 256) {
        int f = i >> 6, kk = i & 63;
        wt[f][kk] = Wfc[f * HH + k0 + kk];
    }
    __syncthreads();
    const int kk = tid & 63;
    const int rr = tid >> 6;           // 0..3
    for (int r = r0 + rr; r < r0 + 256; r += 4) {
        int j = r >> 2, gg = r & 3, srow = gg * HH + j;
        const float* wi = Wih_d + srow * FF;
        float s = Whh_d[(size_t)srow * HH + k0 + kk];
#pragma unroll 16
        for (int f = 0; f < 64; f++) s += wi[f] * wt[f][kk];
        g_B_de[(size_t)r * HH + k0 + kk] = __float2half_rn(s);
    }
    if (blockIdx.x == 0) {
        for (int r = r0 + tid; r < r0 + 256; r += 256) {
            int j = r >> 2, gg = r & 3, srow = gg * HH + j;
            float s = bih_d[srow] + bhh_d[srow];
            const float* wi = Wih_d + srow * FF;
#pragma unroll 16
            for (int f = 0; f < 64; f++) s += wi[f] * bfc[f];
            g_br_de[r] = s;
        }
    }
}

__global__ void prep_x(const float* __restrict__ x)
{
    const int total = SS * BB * FF;
    for (int idx = blockIdx.x * blockDim.x + threadIdx.x; idx < total;
         idx += gridDim.x * blockDim.x) {
        int t = idx / (BB * FF);
        int rem = idx - t * (BB * FF);
        int b = rem / FF, f = rem - b * FF;
        g_X[idx] = __float2half_rn(x[(size_t)b * SS * FF + (size_t)t * FF + f]);
    }
}

__global__ void zero_kernel()
{
    if (blockIdx.x == 0) {
        unsigned* fl = &g_done[0][0][0];
        for (int i = threadIdx.x; i < 2 * 64 * 8; i += blockDim.x) fl[i] = 0;
    }
    for (int i = blockIdx.x * blockDim.x + threadIdx.x; i < BB * HH;
         i += gridDim.x * blockDim.x) {
        g_H[0][i] = __float2half_rn(0.f);
    }
}

// ---------------- persistent fused LSTM, dataflow-synced ----------------
// grid (64, 2) = 128 CTAs, 256 threads (8 warps, 4M x 2N), warp tile 32x32.
// NO global barrier: per-CTA step flags; consumers wait per-chunk on the 8
// producers whose h columns that chunk needs. h is TRIPLE buffered (WAR-safe:
// a CTA reaching epilogue of step s has observed flags >= s from all 64
// producers, so all readers of the buffer being overwritten are done).
__global__ __launch_bounds__(256, 1)
void lstm_persistent(const float* __restrict__ Wfc, const float* __restrict__ bfc,
                     float* __restrict__ out)
{
    extern __shared__ __align__(128) char smem[];
    const uint32_t sb = smem_u32(smem);
    const int tid  = threadIdx.x;
    const int lane = tid & 31;
    const int wid  = tid >> 5;
    const int wm   = wid & 3;          // 0..3 (M)  -> pair id
    const int wn   = wid >> 2;         // 0..1 (N)
    const int ptid = lane + wn * 32;   // 0..63 within pair
    const int bx   = blockIdx.x;       // 0..63 (gate slice / producer id)
    const int by   = blockIdx.y;       // 0..1  (batch group; groups independent)
    const int n0   = bx * BN;
    const int m0   = by * BM;

    const int lr = lane & 15, lh = lane >> 4;
    const int rA0 = wm * 32 + lr, rA1 = rA0 + 16;
    const int rB0 = wn * 32 + lr, rB1 = rB0 + 16;
    const int c2 = lane & 3;
    const bool evenlane = !(c2 & 1);
    const int rbase = lane >> 2;

    float creg[8];                     // persistent cell state
#pragma unroll
    for (int i = 0; i < 8; i++) creg[i] = 0.f;

    // B sub k (64 K-cols, all 128 B-rows) into resident region; tid-mapped (256)
    auto load_bsub = [&](int k, const __half* B_, int bstr) {
#pragma unroll
        for (int i = 0; i < 2; i++) {
            int idx = tid + i * 256;
            int row = idx >> 3, q = idx & 7;
            uint32_t sw = (uint32_t)(row * 128) + ((q ^ (row & 7)) << 4);
            cp16ca(sb + (uint32_t)k * 8192 + sw,
                   B_ + (size_t)(n0 + row) * bstr + k * 64 + q * 8);
        }
    };
    // A sub: PAIR loads its own 32 rows (wm*32..) x 64 K-cols; 4 cp16/thread
    auto load_asub = [&](uint32_t aBase, const __half* ap, int astr, int ak) {
#pragma unroll
        for (int i = 0; i < 4; i++) {
            int idx = ptid + i * 64;       // 0..255
            int row = wm * 32 + (idx >> 3);
            int q = idx & 7;
            uint32_t sw = (uint32_t)(row * 128) + ((q ^ (row & 7)) << 4);
            cp16cg(aBase + sw, ap + (size_t)(m0 + row) * astr + ak + q * 8);
        }
    };

    // initial B residency (encoder weights)
    for (int k = 0; k < 17; k++) load_bsub(k, g_B_enc, KTOT);
    cp_commit();
    cp_wait0();
    __syncthreads();

    bool preloaded = false;

    for (int step = 0; step < NSTEP; step++) {
        const bool de = (step > SS);           // folded decoder steps (K=1024)
        const bool dec = (step >= SS);
        const int pp = step % 3;               // read buffer
        const int po = (step + 1) % 3;         // write buffer
        const int nch = de ? 8 : 9;
        const float* __restrict__ br = de ? g_br_de : (dec ? g_br_dec : g_br_enc);
        const __half* __restrict__ xp = (step < SS)
            ? g_X + (size_t)step * BB * FF
            : g_X + (size_t)(SS - 1) * BB * FF;
        const __half* __restrict__ hp = g_H[pp];

        // chunk-k h producers: 8 CTAs. probe = one non-blocking flag round (warp-wide)
        auto probe = [&](int k) -> bool {
            const int p0 = de ? k * 8 : (k - 1) * 8;
            unsigned v = (unsigned)step;
            if (lane < 8) v = ld_acq(&g_done[by][p0 + lane][0]);
            return __all_sync(0xFFFFFFFFu, v >= (unsigned)step);
        };
        auto poll_block = [&](int k) {
            while (!probe(k)) __nanosleep(20);
        };

        // A chunk c into stage s (pair-scoped). enc chunk0 = x (1 sub); else 2 h subs.
        auto load_chunk = [&](int c, int s) {
            const uint32_t base = sb + BRES + (uint32_t)s * ASTG;
            if (de) {
                load_asub(base,         hp, HH, c * 128);
                load_asub(base + 16384, hp, HH, c * 128 + 64);
            } else if (c == 0) {
                load_asub(base, xp, FF, 0);
            } else {
                load_asub(base,         hp, HH, (c - 1) * 128);
                load_asub(base + 16384, hp, HH, (c - 1) * 128 + 64);
            }
            cp_commit();
        };

        float acc[2][4][4];
#pragma unroll
        for (int mt = 0; mt < 2; mt++)
#pragma unroll
            for (int nt = 0; nt < 4; nt++)
#pragma unroll
                for (int i = 0; i < 4; i++) acc[mt][nt][i] = 0.f;

        if (!preloaded) {
            if (de) poll_block(0);             // de chunk0 consumes h
            load_chunk(0, 0);
        }
        preloaded = false;

        bool rdy = false;                      // readiness of chunk c+1 (from lookahead)
        for (int c = 0; c < nch; c++) {
            const int s = c & 1;
            const int k = c + 1;
            if (k < nch && !rdy) poll_block(k);
            cp_wait0();
            bar_pair(wm);
            if (k < nch) load_chunk(k, s ^ 1);

            const int nsub = (!de && c == 0) ? 1 : 2;
            for (int sub = 0; sub < nsub; sub++) {
                const uint32_t ab = sb + BRES + (uint32_t)s * ASTG + sub * 16384;
                const int bsub = de ? (2 * c + sub) : (c == 0 ? 0 : 2 * c - 1 + sub);
                const uint32_t bb = sb + (uint32_t)bsub * 8192;
#pragma unroll
                for (int ks = 0; ks < 4; ks++) {
                    const int qk = (ks << 1) | lh;
                    uint32_t a0[4], a1[4], b0[4], b1[4];
                    ldsm4(a0, ab + rA0 * 128 + ((qk ^ (rA0 & 7)) << 4));
                    ldsm4(a1, ab + rA1 * 128 + ((qk ^ (rA1 & 7)) << 4));
                    ldsm4(b0, bb + rB0 * 128 + ((qk ^ (rB0 & 7)) << 4));
                    ldsm4(b1, bb + rB1 * 128 + ((qk ^ (rB1 & 7)) << 4));
                    mma16816(acc[0][0], a0, b0[0], b0[2]);
                    mma16816(acc[0][1], a0, b0[1], b0[3]);
                    mma16816(acc[0][2], a0, b1[0], b1[2]);
                    mma16816(acc[0][3], a0, b1[1], b1[3]);
                    mma16816(acc[1][0], a1, b0[0], b0[2]);
                    mma16816(acc[1][1], a1, b0[1], b0[3]);
                    mma16816(acc[1][2], a1, b1[0], b1[2]);
                    mma16816(acc[1][3], a1, b1[1], b1[3]);
                }
            }
            // lookahead: resolve chunk c+2 readiness while MMA pipe drains
            rdy = (k + 1 < nch) ? probe(k + 1) : false;
        }

        // ---------------- fused LSTM epilogue: smem-staged, pair-coalesced ------
        {
            __half* __restrict__ ho = g_H[po];
            __half* hstg = reinterpret_cast<__half*>(smem + HST_OFF) + wm * 512;
#pragma unroll
            for (int mt = 0; mt < 2; mt++) {
#pragma unroll
                for (int nt = 0; nt < 4; nt++) {
                    float* d = acc[mt][nt];
                    float s0 = __shfl_xor_sync(0xFFFFFFFFu, d[0], 1);
                    float s1 = __shfl_xor_sync(0xFFFFFFFFu, d[1], 1);
                    float s2 = __shfl_xor_sync(0xFFFFFFFFu, d[2], 1);
                    float s3 = __shfl_xor_sync(0xFFFFFFFFu, d[3], 1);
                    float q0, q1, q2, q3; int r;
                    if (evenlane) { q0 = d[0]; q1 = d[1]; q2 = s0; q3 = s1; r = rbase; }
                    else          { q0 = s2; q1 = s3; q2 = d[2]; q3 = d[3]; r = rbase + 8; }
                    const int n = n0 + wn * 32 + nt * 8 + (c2 >> 1) * 4;  // gate base
                    const int jloc = wn * 8 + nt * 2 + (c2 >> 1);         // 0..15
                    const int lrow = mt * 16 + r;                         // 0..31
                    const float4 bb4 = *reinterpret_cast<const float4*>(br + n);
                    float iv = sigf(q0 + bb4.x);
                    float fv = sigf(q1 + bb4.y);
                    float gv = tanhf_(q2 + bb4.z);
                    float ov = sigf(q3 + bb4.w);
                    float cn = fv * creg[mt * 4 + nt] + iv * gv;
                    creg[mt * 4 + nt] = cn;
                    hstg[lrow * 16 + jloc] = __float2half_rn(ov * tanhf_(cn));
                }
            }
            bar_pair(wm);
            // coalesced store: 32 rows x 32B per pair; 1 STG.16 per thread
            {
                int row = ptid >> 1, half = ptid & 1;
                uint4 v = *reinterpret_cast<const uint4*>(hstg + row * 16 + half * 8);
                int b = m0 + wm * 32 + row;
                *reinterpret_cast<uint4*>(ho + (size_t)b * HH + (n0 >> 2) + half * 8) = v;
            }
        }

        // publish step completion (release): h slice of this step is visible
        __threadfence();
        __syncthreads();
        if (tid == 0) st_rel(&g_done[by][bx][0], (unsigned)(step + 1));

        // preload next step's x chunk (stage 0, pair rows)
        if (step + 1 <= SS) {
            const __half* nx = (step + 1 < SS) ? (g_X + (size_t)(step + 1) * BB * FF)
                                               : (g_X + (size_t)(SS - 1) * BB * FF);
            load_asub(sb + BRES, nx, FF, 0);   // stage 0, sub 0 (own pair rows)
            cp_commit();
            preloaded = true;
        }

        // phase-transition B reloads (2 steps total; CTA-local sync)
        if (step + 1 == SS || step + 1 == SS + 1) {
            __syncthreads();               // all pairs done reading resident B
            if (step + 1 == SS) for (int k = 0; k < 17; k++) load_bsub(k, g_B_dec, KTOT);
            else                for (int k = 0; k < 16; k++) load_bsub(k, g_B_de, HH);
            cp_commit();
            cp_wait0();                    // also drains the x preload (harmless)
            __syncthreads();
        }

        if (dec) {
            // ---------------- pred = h_t @ Wfc^T + bfc (output only) ------------
            // needs h of step `step` from ALL 64 group producers: wait flags >= step+1
            const unsigned tgt = (unsigned)(step + 1);
            if (wid == 0) {
                for (;;) {
                    unsigned a = ld_acq(&g_done[by][lane][0]);
                    unsigned b2 = ld_acq(&g_done[by][lane + 32][0]);
                    if (__all_sync(0xFFFFFFFFu, (a >= tgt) && (b2 >= tgt))) break;
                    __nanosleep(20);
                }
            }
            __syncthreads();

            const int tdec = step - SS;
            __half* fcb = reinterpret_cast<__half*>(smem + HST_OFF);
            const int b0 = (by * 64 + bx) * 2;
            const __half* hsrc = g_H[po];
            for (int i = tid; i < 256; i += 256) {
                int rrow = i >> 7, o = i & 127;
                uint4 v = __ldcg(reinterpret_cast<const uint4*>(
                    hsrc + (size_t)(b0 + rrow) * HH) + o);
                reinterpret_cast<uint4*>(fcb)[i] = v;
            }
            __syncthreads();
            if (tid < 128) {
                int bl_ = tid >> 6, f = tid & 63;
                const float4* w4 = reinterpret_cast<const float4*>(Wfc + (size_t)f * HH);
                const __half2* h2 = reinterpret_cast<const __half2*>(fcb + bl_ * HH);
                float s = bfc[f];
#pragma unroll 4
                for (int k = 0; k < HH / 4; k++) {
                    float4 wv = w4[k];
                    float2 fa = __half22float2(h2[2 * k]);
                    float2 fb = __half22float2(h2[2 * k + 1]);
                    s += wv.x * fa.x + wv.y * fa.y + wv.z * fb.x + wv.w * fb.y;
                }
                int b = b0 + bl_;
                out[(size_t)b * TT * FF + (size_t)tdec * FF + f] = s;
            }
            __syncthreads();   // fcb region reused as staging next step
        }
    }
}

// ---------------- launch ----------------
extern "C" void kernel_launch(void* const* d_in, const int* in_sizes, int n_in,
                              void* d_out, int out_size)
{
    const float* x     = (const float*)d_in[0];
    const float* Wih_e = (const float*)d_in[1];
    const float* Whh_e = (const float*)d_in[2];
    const float* bih_e = (const float*)d_in[3];
    const float* bhh_e = (const float*)d_in[4];
    const float* Wih_d = (const float*)d_in[5];
    const float* Whh_d = (const float*)d_in[6];
    const float* bih_d = (const float*)d_in[7];
    const float* bhh_d = (const float*)d_in[8];
    const float* Wfc   = (const float*)d_in[9];
    const float* bfc   = (const float*)d_in[10];
    float* out = (float*)d_out;

    cudaFuncSetAttribute(lstm_persistent, cudaFuncAttributeMaxDynamicSharedMemorySize, SMEM_BYTES);

    prep_w<<<1024, 256>>>(Wih_e, Whh_e, bih_e, bhh_e, 0);
    prep_w<<<1024, 256>>>(Wih_d, Whh_d, bih_d, bhh_d, 1);
    { dim3 g(16, 16); prep_wcomb<<<g, 256>>>(Wih_d, Whh_d, bih_d, bhh_d, Wfc, bfc); }
    prep_x<<<1024, 256>>>(x);
    zero_kernel<<<512, 256>>>();

    dim3 grid(GG / BN, BB / BM);   // (64, 2) = 128 CTAs, one wave
    lstm_persistent<<<grid, 256, SMEM_BYTES>>>(Wfc, bfc, out);
}

// round 17
// speedup vs baseline: 1.1271x; 1.1271x over previous
#include <cuda_runtime.h>
#include <cuda_fp16.h>
#include <cstdint>
#include <cstddef>

// Problem constants
#define BB 256      // batch
#define SS 512      // encoder sequence length
#define FF 64       // feature dim
#define HH 1024     // hidden dim
#define GG 4096     // 4*H gate rows
#define KTOT 1088   // F + H
#define TT 64       // prediction length
#define NSTEP (SS + TT)

// Tiling: B (weights) smem-resident (17 x 8KB); A 5-stage pipelined 16KB subs
#define BM 128
#define BN 64
#define BRES (17 * 8192)               // resident B: 139,264 B
#define NAST 5                         // A pipeline stages
#define SMEM_BYTES (BRES + NAST * 16384)   // 221,184 B

// ---------------- device globals ----------------
__device__ __align__(16) __half g_B_enc[GG * KTOT];   // enc weights fp16, rows j*4+g, K-major
__device__ __align__(16) __half g_B_dec[GG * KTOT];   // dec step-SS weights (has x part)
__device__ __align__(16) __half g_B_de[GG * HH];      // dec folded weights: Whh + Wih@Wfc
__device__ __align__(16) float g_br_enc[GG];          // combined bias, reordered
__device__ __align__(16) float g_br_dec[GG];
__device__ __align__(16) float g_br_de[GG];           // folded bias: b_dec + Wih@bfc
__device__ __align__(16) __half g_X[SS * BB * FF];    // encoder x, [t][b][f], fp16
__device__ __align__(16) __half g_H[2][BB * HH];      // hidden state fp16 (ping-pong)
__device__ unsigned g_bars[32];                       // distributed barrier counters

// ---------------- helpers ----------------
__device__ __forceinline__ uint32_t smem_u32(const void* p) {
    return (uint32_t)__cvta_generic_to_shared(p);
}
// L2-only: activations change across steps (persistent kernel -> no L1 flush)
__device__ __forceinline__ void cp16cg(uint32_t dst, const void* src) {
    asm volatile("cp.async.cg.shared.global [%0], [%1], 16;\n" :: "r"(dst), "l"(src));
}
// L1-cached: immutable weights
__device__ __forceinline__ void cp16ca(uint32_t dst, const void* src) {
    asm volatile("cp.async.ca.shared.global [%0], [%1], 16;\n" :: "r"(dst), "l"(src));
}
__device__ __forceinline__ void cp_commit() { asm volatile("cp.async.commit_group;\n"); }
__device__ __forceinline__ void cp_wait0()  { asm volatile("cp.async.wait_group 0;\n" ::: "memory"); }
// wait until at most n groups pending (n computed at runtime, small)
__device__ __forceinline__ void cp_wait_n(int n) {
    switch (n) {
    case 0: asm volatile("cp.async.wait_group 0;\n" ::: "memory"); break;
    case 1: asm volatile("cp.async.wait_group 1;\n" ::: "memory"); break;
    case 2: asm volatile("cp.async.wait_group 2;\n" ::: "memory"); break;
    default: asm volatile("cp.async.wait_group 3;\n" ::: "memory"); break;
    }
}

__device__ __forceinline__ float sigf(float x)   { return 1.f / (1.f + __expf(-x)); }
__device__ __forceinline__ float tanhf_(float x) { return 2.f / (1.f + __expf(-2.f * x)) - 1.f; }

__device__ __forceinline__ void ldsm4(uint32_t* r, uint32_t addr) {
    asm volatile("ldmatrix.sync.aligned.m8n8.x4.shared.b16 {%0,%1,%2,%3}, [%4];"
        : "=r"(r[0]), "=r"(r[1]), "=r"(r[2]), "=r"(r[3]) : "r"(addr));
}
__device__ __forceinline__ void mma16816(float* d, const uint32_t* a, uint32_t b0, uint32_t b1) {
    asm volatile(
        "mma.sync.aligned.m16n8k16.row.col.f32.f16.f16.f32 "
        "{%0,%1,%2,%3}, {%4,%5,%6,%7}, {%8,%9}, {%0,%1,%2,%3};"
        : "+f"(d[0]), "+f"(d[1]), "+f"(d[2]), "+f"(d[3])
        : "r"(a[0]), "r"(a[1]), "r"(a[2]), "r"(a[3]), "r"(b0), "r"(b1));
}

// pair barrier: the two warps sharing wm (64 threads), named barrier id wm+1
__device__ __forceinline__ void bar_pair(int wm) {
    asm volatile("bar.sync %0, %1;" :: "r"(wm + 1), "r"(64) : "memory");
}

// distributed grid barrier: 128 CTAs over 32 counters (4 each); warp0 polls all
__device__ __forceinline__ void grid_barrier(int cta, unsigned target4) {
    __threadfence();
    __syncthreads();
    if (threadIdx.x == 0) atomicAdd(&g_bars[cta & 31], 1u);
    if (threadIdx.x < 32) {
        unsigned v;
        for (;;) {
            asm volatile("ld.global.cg.u32 %0, [%1];"
                         : "=r"(v) : "l"(g_bars + threadIdx.x) : "memory");
            if (__all_sync(0xFFFFFFFFu, v >= target4)) break;
            __nanosleep(20);
        }
    }
    __syncthreads();
    __threadfence();
}

// ---------------- prep kernels ----------------
__global__ void prep_w(const float* __restrict__ Wih, const float* __restrict__ Whh,
                       const float* __restrict__ bih, const float* __restrict__ bhh,
                       int dec)
{
    __half* B = dec ? g_B_dec : g_B_enc;
    float* br = dec ? g_br_dec : g_br_enc;
    const int total = GG * KTOT;
    for (int idx = blockIdx.x * blockDim.x + threadIdx.x; idx < total;
         idx += gridDim.x * blockDim.x) {
        int r = idx / KTOT, k = idx - r * KTOT;
        int j = r >> 2, gg = r & 3;
        int srow = gg * HH + j;
        float w = (k < FF) ? Wih[srow * FF + k] : Whh[(size_t)srow * HH + (k - FF)];
        B[idx] = __float2half_rn(w);
    }
    for (int r = blockIdx.x * blockDim.x + threadIdx.x; r < GG;
         r += gridDim.x * blockDim.x) {
        int j = r >> 2, gg = r & 3;
        br[r] = bih[gg * HH + j] + bhh[gg * HH + j];
    }
}

// folded decoder weights: W_eff = W_hh_dec + W_ih_dec @ Wfc ; b_eff = b_dec + W_ih_dec @ bfc
__global__ void prep_wcomb(const float* __restrict__ Wih_d, const float* __restrict__ Whh_d,
                           const float* __restrict__ bih_d, const float* __restrict__ bhh_d,
                           const float* __restrict__ Wfc, const float* __restrict__ bfc)
{
    __shared__ float wt[64][65];       // Wfc[f][k0+kk]
    const int k0 = blockIdx.x * 64;
    const int r0 = blockIdx.y * 256;
    const int tid = threadIdx.x;
    for (int i = tid; i < 64 * 64; i += 256) {
        int f = i >> 6, kk = i & 63;
        wt[f][kk] = Wfc[f * HH + k0 + kk];
    }
    __syncthreads();
    const int kk = tid & 63;
    const int rr = tid >> 6;           // 0..3
    for (int r = r0 + rr; r < r0 + 256; r += 4) {
        int j = r >> 2, gg = r & 3, srow = gg * HH + j;
        const float* wi = Wih_d + srow * FF;
        float s = Whh_d[(size_t)srow * HH + k0 + kk];
#pragma unroll 16
        for (int f = 0; f < 64; f++) s += wi[f] * wt[f][kk];
        g_B_de[(size_t)r * HH + k0 + kk] = __float2half_rn(s);
    }
    if (blockIdx.x == 0) {
        for (int r = r0 + tid; r < r0 + 256; r += 256) {
            int j = r >> 2, gg = r & 3, srow = gg * HH + j;
            float s = bih_d[srow] + bhh_d[srow];
            const float* wi = Wih_d + srow * FF;
#pragma unroll 16
            for (int f = 0; f < 64; f++) s += wi[f] * bfc[f];
            g_br_de[r] = s;
        }
    }
}

__global__ void prep_x(const float* __restrict__ x)
{
    const int total = SS * BB * FF;
    for (int idx = blockIdx.x * blockDim.x + threadIdx.x; idx < total;
         idx += gridDim.x * blockDim.x) {
        int t = idx / (BB * FF);
        int rem = idx - t * (BB * FF);
        int b = rem / FF, f = rem - b * FF;
        g_X[idx] = __float2half_rn(x[(size_t)b * SS * FF + (size_t)t * FF + f]);
    }
}

__global__ void zero_kernel()
{
    if (blockIdx.x == 0 && threadIdx.x < 32) g_bars[threadIdx.x] = 0;
    for (int i = blockIdx.x * blockDim.x + threadIdx.x; i < BB * HH;
         i += gridDim.x * blockDim.x) {
        g_H[0][i] = __float2half_rn(0.f);
    }
}

// ---------------- persistent fused LSTM ----------------
// grid (64, 2) = 128 CTAs, 256 threads (8 warps, 4M x 2N), warp tile 32x32.
// B smem-resident. A: 5-stage pipeline of 64-col subs, issue depth 4, pair-scoped
// loads. Distributed grid barrier. Coalesced h stores. c in registers.
__global__ __launch_bounds__(256, 1)
void lstm_persistent(const float* __restrict__ Wfc, const float* __restrict__ bfc,
                     float* __restrict__ out)
{
    extern __shared__ __align__(128) char smem[];
    const uint32_t sb = smem_u32(smem);
    const int tid  = threadIdx.x;
    const int lane = tid & 31;
    const int wid  = tid >> 5;
    const int wm   = wid & 3;          // 0..3 (M)  -> pair id
    const int wn   = wid >> 2;         // 0..1 (N)
    const int ptid = lane + wn * 32;   // 0..63 within pair
    const int n0   = blockIdx.x * BN;
    const int m0   = blockIdx.y * BM;
    const int cta  = blockIdx.y * 64 + blockIdx.x;

    const int lr = lane & 15, lh = lane >> 4;
    const int rA0 = wm * 32 + lr, rA1 = rA0 + 16;
    const int rB0 = wn * 32 + lr, rB1 = rB0 + 16;
    const int c2 = lane & 3;
    const bool evenlane = !(c2 & 1);
    const int rbase = lane >> 2;

    float creg[8];                     // persistent cell state
#pragma unroll
    for (int i = 0; i < 8; i++) creg[i] = 0.f;

    // B sub k (64 K-cols, all 128 B-rows) into resident region; tid-mapped (256)
    auto load_bsub = [&](int k, const __half* B_, int bstr) {
#pragma unroll
        for (int i = 0; i < 2; i++) {
            int idx = tid + i * 256;
            int row = idx >> 3, q = idx & 7;
            uint32_t sw = (uint32_t)(row * 128) + ((q ^ (row & 7)) << 4);
            cp16ca(sb + (uint32_t)k * 8192 + sw,
                   B_ + (size_t)(n0 + row) * bstr + k * 64 + q * 8);
        }
    };
    // A sub: PAIR loads its own 32 rows (wm*32..) x 64 K-cols; 4 cp16/thread
    auto load_asub = [&](uint32_t aBase, const __half* ap, int astr, int ak) {
#pragma unroll
        for (int i = 0; i < 4; i++) {
            int idx = ptid + i * 64;       // 0..255
            int row = wm * 32 + (idx >> 3);
            int q = idx & 7;
            uint32_t sw = (uint32_t)(row * 128) + ((q ^ (row & 7)) << 4);
            cp16cg(aBase + sw, ap + (size_t)(m0 + row) * astr + ak + q * 8);
        }
    };

    // initial B residency (encoder weights)
    for (int k = 0; k < 17; k++) load_bsub(k, g_B_enc, KTOT);
    cp_commit();
    cp_wait0();
    __syncthreads();

    bool preloaded = false;

    for (int step = 0; step < NSTEP; step++) {
        const bool de = (step > SS);           // folded decoder steps (K=1024)
        const bool dec = (step >= SS);
        const int pp = step & 1;
        const int nsub = de ? 16 : 17;
        const float* __restrict__ br = de ? g_br_de : (dec ? g_br_dec : g_br_enc);
        const __half* __restrict__ xp = (step < SS)
            ? g_X + (size_t)step * BB * FF
            : g_X + (size_t)(SS - 1) * BB * FF;
        const __half* __restrict__ hp = g_H[pp];

        // issue A sub c into stage c%NAST (one commit group per sub)
        auto issue_sub = [&](int c) {
            const uint32_t base = sb + BRES + (uint32_t)(c % NAST) * 16384;
            if (de)           load_asub(base, hp, HH, c * 64);
            else if (c == 0)  load_asub(base, xp, FF, 0);
            else              load_asub(base, hp, HH, (c - 1) * 64);
            cp_commit();
        };

        float acc[2][4][4];
#pragma unroll
        for (int mt = 0; mt < 2; mt++)
#pragma unroll
            for (int nt = 0; nt < 4; nt++)
#pragma unroll
                for (int i = 0; i < 4; i++) acc[mt][nt][i] = 0.f;

        if (!preloaded) issue_sub(0);
        preloaded = false;
        issue_sub(1); issue_sub(2); issue_sub(3);

        for (int c = 0; c < nsub; c++) {
            const int rem = nsub - 1 - c;
            cp_wait_n(rem < 3 ? rem : 3);      // ensures sub c arrived (my loads)
            bar_pair(wm);                      // partner's sub-c loads + frees stage (c-1)%5
            if (c + 4 < nsub) issue_sub(c + 4);

            const uint32_t ab = sb + BRES + (uint32_t)(c % NAST) * 16384;
            const uint32_t bb = sb + (uint32_t)c * 8192;
#pragma unroll
            for (int ks = 0; ks < 4; ks++) {
                const int qk = (ks << 1) | lh;
                uint32_t a0[4], a1[4], b0[4], b1[4];
                ldsm4(a0, ab + rA0 * 128 + ((qk ^ (rA0 & 7)) << 4));
                ldsm4(a1, ab + rA1 * 128 + ((qk ^ (rA1 & 7)) << 4));
                ldsm4(b0, bb + rB0 * 128 + ((qk ^ (rB0 & 7)) << 4));
                ldsm4(b1, bb + rB1 * 128 + ((qk ^ (rB1 & 7)) << 4));
                mma16816(acc[0][0], a0, b0[0], b0[2]);
                mma16816(acc[0][1], a0, b0[1], b0[3]);
                mma16816(acc[0][2], a0, b1[0], b1[2]);
                mma16816(acc[0][3], a0, b1[1], b1[3]);
                mma16816(acc[1][0], a1, b0[0], b0[2]);
                mma16816(acc[1][1], a1, b0[1], b0[3]);
                mma16816(acc[1][2], a1, b1[0], b1[2]);
                mma16816(acc[1][3], a1, b1[1], b1[3]);
            }
        }

        // ---------------- fused LSTM epilogue: smem-staged, pair-coalesced ------
        // staging reuses A stage-2 region (its sub was consumed many iterations ago)
        {
            __half* __restrict__ ho = g_H[pp ^ 1];
            __half* hstg = reinterpret_cast<__half*>(smem + BRES + 2 * 16384) + wm * 512;
#pragma unroll
            for (int mt = 0; mt < 2; mt++) {
#pragma unroll
                for (int nt = 0; nt < 4; nt++) {
                    float* d = acc[mt][nt];
                    float s0 = __shfl_xor_sync(0xFFFFFFFFu, d[0], 1);
                    float s1 = __shfl_xor_sync(0xFFFFFFFFu, d[1], 1);
                    float s2 = __shfl_xor_sync(0xFFFFFFFFu, d[2], 1);
                    float s3 = __shfl_xor_sync(0xFFFFFFFFu, d[3], 1);
                    float q0, q1, q2, q3; int r;
                    if (evenlane) { q0 = d[0]; q1 = d[1]; q2 = s0; q3 = s1; r = rbase; }
                    else          { q0 = s2; q1 = s3; q2 = d[2]; q3 = d[3]; r = rbase + 8; }
                    const int n = n0 + wn * 32 + nt * 8 + (c2 >> 1) * 4;  // gate base
                    const int jloc = wn * 8 + nt * 2 + (c2 >> 1);         // 0..15
                    const int lrow = mt * 16 + r;                         // 0..31
                    const float4 bb4 = *reinterpret_cast<const float4*>(br + n);
                    float iv = sigf(q0 + bb4.x);
                    float fv = sigf(q1 + bb4.y);
                    float gv = tanhf_(q2 + bb4.z);
                    float ov = sigf(q3 + bb4.w);
                    float cn = fv * creg[mt * 4 + nt] + iv * gv;
                    creg[mt * 4 + nt] = cn;
                    hstg[lrow * 16 + jloc] = __float2half_rn(ov * tanhf_(cn));
                }
            }
            bar_pair(wm);
            // coalesced store: 32 rows x 32B per pair; 1 STG.16 per thread
            {
                int row = ptid >> 1, half = ptid & 1;
                uint4 v = *reinterpret_cast<const uint4*>(hstg + row * 16 + half * 8);
                int b = m0 + wm * 32 + row;
                *reinterpret_cast<uint4*>(ho + (size_t)b * HH + (n0 >> 2) + half * 8) = v;
            }
        }

        // preload next step's x sub (stage 0, pair rows) before the barrier.
        // safe: stage 0 held sub 15 (enc) / sub 15 (de), consumed; pair synced above.
        if (step + 1 <= SS) {
            const __half* nx = (step + 1 < SS) ? (g_X + (size_t)(step + 1) * BB * FF)
                                               : (g_X + (size_t)(SS - 1) * BB * FF);
            load_asub(sb + BRES, nx, FF, 0);
            cp_commit();
            preloaded = true;
        }

        // phase-transition B reloads (2 steps total; CTA-local sync)
        if (step + 1 == SS || step + 1 == SS + 1) {
            __syncthreads();               // all pairs done reading resident B
            if (step + 1 == SS) for (int k = 0; k < 17; k++) load_bsub(k, g_B_dec, KTOT);
            else                for (int k = 0; k < 16; k++) load_bsub(k, g_B_de, HH);
            cp_commit();
            cp_wait0();                    // also drains the x preload (harmless)
            __syncthreads();
        }

        grid_barrier(cta, 4u * (unsigned)(step + 1));

        if (dec) {
            // ---------------- pred = h_t @ Wfc^T + bfc (output only) ------------
            // fc scratch reuses A stage-1 region (dead; rewritten only next step)
            const int tdec = step - SS;
            __half* fcb = reinterpret_cast<__half*>(smem + BRES + 16384);
            const int b0 = cta * 2;
            const __half* hsrc = g_H[pp ^ 1];
            for (int i = tid; i < 256; i += 256) {
                int rrow = i >> 7, o = i & 127;
                uint4 v = __ldcg(reinterpret_cast<const uint4*>(
                    hsrc + (size_t)(b0 + rrow) * HH) + o);
                reinterpret_cast<uint4*>(fcb)[i] = v;
            }
            __syncthreads();
            if (tid < 128) {
                int bl_ = tid >> 6, f = tid & 63;
                const float4* w4 = reinterpret_cast<const float4*>(Wfc + (size_t)f * HH);
                const __half2* h2 = reinterpret_cast<const __half2*>(fcb + bl_ * HH);
                float s = bfc[f];
#pragma unroll 4
                for (int k = 0; k < HH / 4; k++) {
                    float4 wv = w4[k];
                    float2 fa = __half22float2(h2[2 * k]);
                    float2 fb = __half22float2(h2[2 * k + 1]);
                    s += wv.x * fa.x + wv.y * fa.y + wv.z * fb.x + wv.w * fb.y;
                }
                int b = b0 + bl_;
                out[(size_t)b * TT * FF + (size_t)tdec * FF + f] = s;
            }
            __syncthreads();   // fcb region rewritten by next step's prologue
        }
    }
}

// ---------------- launch ----------------
extern "C" void kernel_launch(void* const* d_in, const int* in_sizes, int n_in,
                              void* d_out, int out_size)
{
    const float* x     = (const float*)d_in[0];
    const float* Wih_e = (const float*)d_in[1];
    const float* Whh_e = (const float*)d_in[2];
    const float* bih_e = (const float*)d_in[3];
    const float* bhh_e = (const float*)d_in[4];
    const float* Wih_d = (const float*)d_in[5];
    const float* Whh_d = (const float*)d_in[6];
    const float* bih_d = (const float*)d_in[7];
    const float* bhh_d = (const float*)d_in[8];
    const float* Wfc   = (const float*)d_in[9];
    const float* bfc   = (const float*)d_in[10];
    float* out = (float*)d_out;

    cudaFuncSetAttribute(lstm_persistent, cudaFuncAttributeMaxDynamicSharedMemorySize, SMEM_BYTES);

    prep_w<<<1024, 256>>>(Wih_e, Whh_e, bih_e, bhh_e, 0);
    prep_w<<<1024, 256>>>(Wih_d, Whh_d, bih_d, bhh_d, 1);
    { dim3 g(16, 16); prep_wcomb<<<g, 256>>>(Wih_d, Whh_d, bih_d, bhh_d, Wfc, bfc); }
    prep_x<<<1024, 256>>>(x);
    zero_kernel<<<512, 256>>>();

    dim3 grid(GG / BN, BB / BM);   // (64, 2) = 128 CTAs, one wave
    lstm_persistent<<<grid, 256, SMEM_BYTES>>>(Wfc, bfc, out);
}